// round 3
// baseline (speedup 1.0000x reference)
#include <cuda_runtime.h>
#include <math.h>

#define N_NODES 50000
#define N_EDGES 800000
#define N_GRAPHS 128
#define IN_DIM 100
#define HID 256
#define STEPS 5

// ---------------- scratch (device globals; no allocation) ----------------
__device__ float d_h[N_NODES * HID];
__device__ float d_m[N_NODES * HID];
__device__ float d_agg[N_NODES * HID];
__device__ float d_gi[N_NODES * 3 * HID];
__device__ float d_gh[N_NODES * 3 * HID];
__device__ float d_t1[N_NODES * (HID / 2)];
__device__ float d_pool[N_GRAPHS * 2 * HID];

// ---------------- generic tiled SGEMM: C = A(MxK) * B (+bias, optional relu)
// TB=false: B is [K,N] row-major (NN).  TB=true: B is [N,K] row-major (NT).
template <bool TB, bool RELU>
__global__ void gemm_kernel(const float* __restrict__ A, const float* __restrict__ B,
                            const float* __restrict__ bias, float* __restrict__ C,
                            int M, int N, int K) {
    __shared__ float As[8][132];
    __shared__ float Bs[8][132];
    const int tid = threadIdx.x;          // 256 threads
    const int tx = tid & 15;
    const int ty = tid >> 4;
    const int row0 = blockIdx.y * 128;
    const int col0 = blockIdx.x * 128;

    float acc[8][8];
#pragma unroll
    for (int i = 0; i < 8; i++)
#pragma unroll
        for (int j = 0; j < 8; j++) acc[i][j] = 0.f;

    for (int k0 = 0; k0 < K; k0 += 8) {
        // load A tile: 128 rows x 8 k
#pragma unroll
        for (int it = 0; it < 4; it++) {
            int l = tid + it * 256;
            int m = l >> 3;
            int k = l & 7;
            float v = 0.f;
            if (row0 + m < M && k0 + k < K) v = A[(size_t)(row0 + m) * K + (k0 + k)];
            As[k][m] = v;
        }
        // load B tile: 8 k x 128 n
#pragma unroll
        for (int it = 0; it < 4; it++) {
            int l = tid + it * 256;
            float v = 0.f;
            if (TB) {
                int n = l >> 3;
                int k = l & 7;
                if (col0 + n < N && k0 + k < K) v = B[(size_t)(col0 + n) * K + (k0 + k)];
                Bs[k][n] = v;
            } else {
                int k = l >> 7;
                int n = l & 127;
                if (col0 + n < N && k0 + k < K) v = B[(size_t)(k0 + k) * N + (col0 + n)];
                Bs[k][n] = v;
            }
        }
        __syncthreads();
#pragma unroll
        for (int kk = 0; kk < 8; kk++) {
            float ar[8], br[8];
#pragma unroll
            for (int i = 0; i < 8; i++) ar[i] = As[kk][ty + 16 * i];
#pragma unroll
            for (int j = 0; j < 8; j++) br[j] = Bs[kk][tx + 16 * j];
#pragma unroll
            for (int i = 0; i < 8; i++)
#pragma unroll
                for (int j = 0; j < 8; j++) acc[i][j] += ar[i] * br[j];
        }
        __syncthreads();
    }

#pragma unroll
    for (int i = 0; i < 8; i++) {
        int r = row0 + ty + 16 * i;
        if (r >= M) continue;
#pragma unroll
        for (int j = 0; j < 8; j++) {
            int c = col0 + tx + 16 * j;
            if (c >= N) continue;
            float v = acc[i][j] + (bias ? bias[c] : 0.f);
            if (RELU) v = fmaxf(v, 0.f);
            C[(size_t)r * N + c] = v;
        }
    }
}

// ---------------- zero buffer ----------------
__global__ void zero_kernel(float4* p, long n4) {
    long i = (long)blockIdx.x * blockDim.x + threadIdx.x;
    if (i < n4) p[i] = make_float4(0.f, 0.f, 0.f, 0.f);
}

// ---------------- scatter add: agg[dst[e]] += m[src[e]] ----------------
__global__ void scatter_add_kernel(const float* __restrict__ m,
                                   const int* __restrict__ src,
                                   const int* __restrict__ dst,
                                   float* __restrict__ agg) {
    long idx = (long)blockIdx.x * blockDim.x + threadIdx.x;
    long e = idx >> 6;  // 64 threads per edge, 4 floats each
    if (e >= N_EDGES) return;
    int d4 = (int)(idx & 63) << 2;
    int s = src[e];
    int d = dst[e];
    float4 v = *(const float4*)(m + (size_t)s * HID + d4);
    float* p = agg + (size_t)d * HID + d4;
    atomicAdd(p + 0, v.x);
    atomicAdd(p + 1, v.y);
    atomicAdd(p + 2, v.z);
    atomicAdd(p + 3, v.w);
}

// ---------------- GRU cell elementwise ----------------
__global__ void gru_kernel(const float* __restrict__ gi, const float* __restrict__ gh,
                           float* __restrict__ h) {
    long idx = (long)blockIdx.x * blockDim.x + threadIdx.x;
    if (idx >= (long)N_NODES * HID) return;
    int n = (int)(idx / HID);
    int d = (int)(idx % HID);
    const float* gin = gi + (size_t)n * 3 * HID;
    const float* ghn = gh + (size_t)n * 3 * HID;
    float i_r = gin[d], i_z = gin[HID + d], i_n = gin[2 * HID + d];
    float h_r = ghn[d], h_z = ghn[HID + d], h_n = ghn[2 * HID + d];
    float r = 1.f / (1.f + expf(-(i_r + h_r)));
    float z = 1.f / (1.f + expf(-(i_z + h_z)));
    float nn = tanhf(i_n + r * h_n);
    h[idx] = (1.f - z) * nn + z * h[idx];
}

// ---------------- in-place relu ----------------
__global__ void relu_kernel(float* __restrict__ p, long n) {
    long i = (long)blockIdx.x * blockDim.x + threadIdx.x;
    if (i < n) p[i] = fmaxf(p[i], 0.f);
}

// ---------------- attention scalar: a = sigmoid(t1 @ Wa2 + ba2) ----------------
__global__ void attn_a_kernel(const float* __restrict__ t1, const float* __restrict__ Wa2,
                              const float* __restrict__ ba2, float* __restrict__ a) {
    long idx = (long)blockIdx.x * blockDim.x + threadIdx.x;
    int warp = (int)(idx >> 5);
    int lane = (int)(idx & 31);
    if (warp >= N_NODES) return;
    float s = 0.f;
#pragma unroll
    for (int k = lane; k < HID / 2; k += 32) s += t1[(size_t)warp * (HID / 2) + k] * Wa2[k];
#pragma unroll
    for (int o = 16; o > 0; o >>= 1) s += __shfl_xor_sync(0xFFFFFFFFu, s, o);
    if (lane == 0) a[warp] = 1.f / (1.f + expf(-(s + ba2[0])));
}

// ---------------- segmented mean/max pooling (batch is sorted) ----------------
__global__ void pool_kernel(const float* __restrict__ h, const float* __restrict__ a,
                            const int* __restrict__ batch, float* __restrict__ pool) {
    int g = blockIdx.x;
    int d = threadIdx.x;  // 256 threads = HID dims
    __shared__ int s_lo, s_hi;
    if (d == 0) {
        int lo = 0, hi = N_NODES;
        while (lo < hi) { int mid = (lo + hi) >> 1; if (batch[mid] < g) lo = mid + 1; else hi = mid; }
        s_lo = lo;
        lo = 0; hi = N_NODES;
        while (lo < hi) { int mid = (lo + hi) >> 1; if (batch[mid] < g + 1) lo = mid + 1; else hi = mid; }
        s_hi = lo;
    }
    __syncthreads();
    int lo = s_lo, hi = s_hi;
    float sum = 0.f, mx = 0.f;  // wx >= 0 (relu * sigmoid), so 0-init max matches ref
    for (int i = lo; i < hi; i++) {
        float w = h[(size_t)i * HID + d] * a[i];
        sum += w;
        mx = fmaxf(mx, w);
    }
    int cnt = hi - lo;
    pool[(size_t)g * 2 * HID + d] = sum / (float)(cnt > 1 ? cnt : 1);
    pool[(size_t)g * 2 * HID + HID + d] = (cnt > 0) ? mx : 0.f;
}

// ---------------- classifier MLP: 512 -> 256 -> 128 -> 2 ----------------
__global__ void classifier_kernel(const float* __restrict__ pool,
                                  const float* __restrict__ Wc1, const float* __restrict__ bc1,
                                  const float* __restrict__ Wc2, const float* __restrict__ bc2,
                                  const float* __restrict__ Wc3, const float* __restrict__ bc3,
                                  float* __restrict__ preds) {
    int g = blockIdx.x;
    int t = threadIdx.x;  // 256 threads
    __shared__ float sg[2 * HID];
    __shared__ float t1[HID];
    __shared__ float t2[HID / 2];
    sg[t] = pool[(size_t)g * 2 * HID + t];
    sg[t + HID] = pool[(size_t)g * 2 * HID + HID + t];
    __syncthreads();
    {
        float acc = bc1[t];
        for (int k = 0; k < 2 * HID; k++) acc += sg[k] * Wc1[(size_t)k * HID + t];
        t1[t] = fmaxf(acc, 0.f);
    }
    __syncthreads();
    if (t < HID / 2) {
        float acc = bc2[t];
        for (int k = 0; k < HID; k++) acc += t1[k] * Wc2[(size_t)k * (HID / 2) + t];
        t2[t] = fmaxf(acc, 0.f);
    }
    __syncthreads();
    if (t < 2) {
        float acc = bc3[t];
        for (int k = 0; k < HID / 2; k++) acc += t2[k] * Wc3[(size_t)k * 2 + t];
        preds[g * 2 + t] = acc;
    }
}

// ---------------- launch ----------------
extern "C" void kernel_launch(void* const* d_in, const int* in_sizes, int n_in,
                              void* d_out, int out_size) {
    const float* x     = (const float*)d_in[0];
    const int*   edge  = (const int*)d_in[1];
    const int*   batch = (const int*)d_in[2];
    const float* W_in  = (const float*)d_in[3];
    const float* b_in  = (const float*)d_in[4];
    const float* ggc_w = (const float*)d_in[5];
    const float* W_ih  = (const float*)d_in[6];
    const float* W_hh  = (const float*)d_in[7];
    const float* b_ih  = (const float*)d_in[8];
    const float* b_hh  = (const float*)d_in[9];
    const float* Wa1   = (const float*)d_in[10];
    const float* ba1   = (const float*)d_in[11];
    const float* Wa2   = (const float*)d_in[12];
    const float* ba2   = (const float*)d_in[13];
    const float* Wc1   = (const float*)d_in[14];
    const float* bc1   = (const float*)d_in[15];
    const float* Wc2   = (const float*)d_in[16];
    const float* bc2   = (const float*)d_in[17];
    const float* Wc3   = (const float*)d_in[18];
    const float* bc3   = (const float*)d_in[19];

    float* out   = (float*)d_out;
    float* preds = out;                 // [128, 2]
    float* a_out = out + N_GRAPHS * 2;  // [50000]

    float *h, *m, *agg, *gi, *gh, *t1, *pool;
    cudaGetSymbolAddress((void**)&h, d_h);
    cudaGetSymbolAddress((void**)&m, d_m);
    cudaGetSymbolAddress((void**)&agg, d_agg);
    cudaGetSymbolAddress((void**)&gi, d_gi);
    cudaGetSymbolAddress((void**)&gh, d_gh);
    cudaGetSymbolAddress((void**)&t1, d_t1);
    cudaGetSymbolAddress((void**)&pool, d_pool);

    const int* src = edge;
    const int* dst = edge + N_EDGES;

    dim3 blk(256);
    auto grid2 = [](int M, int N) { return dim3((N + 127) / 128, (M + 127) / 128); };

    // input projection + relu
    gemm_kernel<false, true><<<grid2(N_NODES, HID), blk>>>(x, W_in, b_in, h, N_NODES, HID, IN_DIM);

    long n4_agg = (long)N_NODES * HID / 4;
    for (int s = 0; s < STEPS; s++) {
        gemm_kernel<false, false><<<grid2(N_NODES, HID), blk>>>(
            h, ggc_w + (size_t)s * HID * HID, nullptr, m, N_NODES, HID, HID);
        zero_kernel<<<(unsigned)((n4_agg + 255) / 256), 256>>>((float4*)agg, n4_agg);
        {
            long tot = (long)N_EDGES * 64;
            scatter_add_kernel<<<(unsigned)((tot + 255) / 256), 256>>>(m, src, dst, agg);
        }
        gemm_kernel<true, false><<<grid2(N_NODES, 3 * HID), blk>>>(agg, W_ih, b_ih, gi, N_NODES, 3 * HID, HID);
        gemm_kernel<true, false><<<grid2(N_NODES, 3 * HID), blk>>>(h, W_hh, b_hh, gh, N_NODES, 3 * HID, HID);
        {
            long tot = (long)N_NODES * HID;
            gru_kernel<<<(unsigned)((tot + 255) / 256), 256>>>(gi, gh, h);
        }
    }

    {
        long tot = (long)N_NODES * HID;
        relu_kernel<<<(unsigned)((tot + 255) / 256), 256>>>(h, tot);
    }

    // attention
    gemm_kernel<false, true><<<grid2(N_NODES, HID / 2), blk>>>(h, Wa1, ba1, t1, N_NODES, HID / 2, HID);
    {
        long tot = (long)N_NODES * 32;
        attn_a_kernel<<<(unsigned)((tot + 255) / 256), 256>>>(t1, Wa2, ba2, a_out);
    }

    // pooling + classifier
    pool_kernel<<<N_GRAPHS, HID>>>(h, a_out, batch, pool);
    classifier_kernel<<<N_GRAPHS, 256>>>(pool, Wc1, bc1, Wc2, bc2, Wc3, bc3, preds);
}

// round 5
// speedup vs baseline: 2.5852x; 2.5852x over previous
#include <cuda_runtime.h>
#include <cuda_bf16.h>
#include <cstdint>
#include <math.h>

#define N_NODES 50000
#define MPAD    50048   // multiple of 128; pad rows stay zero (.bss)
#define N_EDGES 800000
#define N_GRAPHS 128
#define IN_DIM  100
#define HID     256
#define STEPS   5

// ---------------- scratch (device globals; zero-initialized, no allocation) ----
__device__ float d_h [MPAD * HID];
__device__ float d_hs[MPAD * HID];          // scatter accumulator (sum h[src])
__device__ float d_gi[(size_t)N_NODES * 3 * HID];
__device__ float d_gh[(size_t)N_NODES * 3 * HID];
__device__ float d_t1[(size_t)N_NODES * (HID / 2)];
__device__ float d_pool[N_GRAPHS * 2 * HID];

__device__ __nv_bfloat16 d_h_hi [MPAD * HID], d_h_lo [MPAD * HID];
__device__ __nv_bfloat16 d_hs_hi[MPAD * HID], d_hs_lo[MPAD * HID];
__device__ __nv_bfloat16 d_ag_hi[MPAD * HID], d_ag_lo[MPAD * HID];
__device__ __nv_bfloat16 d_x_hi [MPAD * 128], d_x_lo [MPAD * 128];

__device__ __nv_bfloat16 d_wih_hi[768 * 256], d_wih_lo[768 * 256];
__device__ __nv_bfloat16 d_whh_hi[768 * 256], d_whh_lo[768 * 256];
__device__ __nv_bfloat16 d_wt_hi [STEPS * 256 * 256], d_wt_lo [STEPS * 256 * 256];
__device__ __nv_bfloat16 d_wa1_hi[128 * 256], d_wa1_lo[128 * 256];
__device__ __nv_bfloat16 d_win_hi[256 * 128], d_win_lo[256 * 128];

// ================= PTX helpers (all sm_80-baseline; no arch-specific feats) ====
__device__ __forceinline__ uint32_t smem_u32(const void* p) {
    uint32_t a;
    asm("{ .reg .u64 t; cvta.to.shared.u64 t, %1; cvt.u32.u64 %0, t; }" : "=r"(a) : "l"(p));
    return a;
}
__device__ __forceinline__ void cp16(uint32_t s, const void* g) {
    asm volatile("cp.async.cg.shared.global [%0], [%1], 16;" :: "r"(s), "l"(g));
}
#define CP_COMMIT() asm volatile("cp.async.commit_group;" ::: "memory")
#define CP_WAIT(N)  asm volatile("cp.async.wait_group %0;" :: "n"(N) : "memory")

__device__ __forceinline__ void ldm4(uint32_t& r0, uint32_t& r1, uint32_t& r2, uint32_t& r3,
                                     uint32_t a) {
    asm volatile("ldmatrix.sync.aligned.m8n8.x4.shared.b16 {%0,%1,%2,%3}, [%4];"
                 : "=r"(r0), "=r"(r1), "=r"(r2), "=r"(r3) : "r"(a));
}
__device__ __forceinline__ void mma_bf16(float* c, const uint32_t* a, const uint32_t* b) {
    asm volatile(
        "mma.sync.aligned.m16n8k16.row.col.f32.bf16.bf16.f32 "
        "{%0,%1,%2,%3}, {%4,%5,%6,%7}, {%8,%9}, {%0,%1,%2,%3};"
        : "+f"(c[0]), "+f"(c[1]), "+f"(c[2]), "+f"(c[3])
        : "r"(a[0]), "r"(a[1]), "r"(a[2]), "r"(a[3]), "r"(b[0]), "r"(b[1]));
}
__device__ __forceinline__ uint32_t pack_bf2(float a, float b) {
    __nv_bfloat16 x = __float2bfloat16(a), y = __float2bfloat16(b);
    return ((uint32_t)__bfloat16_as_ushort(y) << 16) | (uint32_t)__bfloat16_as_ushort(x);
}

// ================= mma.sync GEMM: C[M, Ntot] = A[M, K] @ B[Ntot, K]^T ==========
// A as bf16 hi/lo [MPAD, K] (K-contig), B as bf16 hi/lo [Ntot, K] (K-contig).
// Split product: AhBh + AhBl + AlBh, fp32 accumulation.
// CTA tile 128x128, 8 warps (warp_m 0..3 x warp_n 0..1), warp tile 32x64.
// K chunk 32, cp.async double-buffered. Smem row stride 80B (conflict-free ldmatrix).
template <int KTOT, bool WF32, bool WBF16, bool RELU>
__global__ __launch_bounds__(256) void mma_gemm(
    const __nv_bfloat16* __restrict__ Ah, const __nv_bfloat16* __restrict__ Al,
    const __nv_bfloat16* __restrict__ Bh, const __nv_bfloat16* __restrict__ Bl,
    const float* __restrict__ bias,
    float* __restrict__ Cf, __nv_bfloat16* __restrict__ Cbh, __nv_bfloat16* __restrict__ Cbl,
    int M, int Ntot)
{
    constexpr int CH = KTOT / 32;
    constexpr int RSTRIDE = 80;          // bytes per 32-element bf16 row (64B data + 16B pad)
    constexpr int MAT = 128 * RSTRIDE;   // 10240 B per matrix per stage
    extern __shared__ char smem[];
    const uint32_t sb = smem_u32(smem);

    const int tid = threadIdx.x;
    const int wid = tid >> 5, lane = tid & 31;
    const int warp_m = wid & 3, warp_n = wid >> 2;
    const int row0 = blockIdx.y * 128;
    const int ncol0 = blockIdx.x * 128;

    float acc[2][8][4];
#pragma unroll
    for (int tm = 0; tm < 2; tm++)
#pragma unroll
        for (int nt = 0; nt < 8; nt++)
#pragma unroll
            for (int c = 0; c < 4; c++) acc[tm][nt][c] = 0.f;

    auto load_stage = [&](int c, int st) {
        const int k0 = c * 32;
        const uint32_t base = sb + st * (4 * MAT);
#pragma unroll
        for (int i = 0; i < 2; i++) {
            int l = tid + i * 256;       // 512 uint4 per matrix
            int row = l >> 2, q = l & 3;
            uint32_t so = (uint32_t)(row * RSTRIDE + q * 16);
            size_t ea = (size_t)(row0 + row) * KTOT + k0 + q * 8;
            size_t eb = (size_t)(ncol0 + row) * KTOT + k0 + q * 8;
            cp16(base + so,           Ah + ea);
            cp16(base + MAT + so,     Al + ea);
            cp16(base + 2 * MAT + so, Bh + eb);
            cp16(base + 3 * MAT + so, Bl + eb);
        }
    };

    load_stage(0, 0);
    CP_COMMIT();

    const int ar = (lane & 7) + ((lane >> 3) & 1) * 8;   // A m-row within 16
    const int akh = lane >> 4;                            // A k-half
    const int bn = (lane >> 4);                           // B tile within pair
    const int bk = (lane >> 3) & 1;                       // B k-half

    for (int c = 0; c < CH; c++) {
        const int st = c & 1;
        if (c + 1 < CH) {
            load_stage(c + 1, st ^ 1);
            CP_COMMIT();
            CP_WAIT(1);
        } else {
            CP_WAIT(0);
        }
        __syncthreads();

        const uint32_t base = sb + st * (4 * MAT);
#pragma unroll
        for (int j = 0; j < 2; j++) {    // two k16 per chunk
            uint32_t ah[2][4], al[2][4];
#pragma unroll
            for (int tm = 0; tm < 2; tm++) {
                uint32_t ao = base + (uint32_t)((warp_m * 32 + tm * 16 + ar) * RSTRIDE +
                                                j * 32 + akh * 16);
                ldm4(ah[tm][0], ah[tm][1], ah[tm][2], ah[tm][3], ao);
                ldm4(al[tm][0], al[tm][1], al[tm][2], al[tm][3], ao + MAT);
            }
            uint32_t bh[4][4], bl[4][4];
#pragma unroll
            for (int q = 0; q < 4; q++) {
                int nrow = warp_n * 64 + (2 * q + bn) * 8 + (lane & 7);
                uint32_t bo = base + 2 * MAT +
                              (uint32_t)(nrow * RSTRIDE + j * 32 + bk * 16);
                ldm4(bh[q][0], bh[q][1], bh[q][2], bh[q][3], bo);
                ldm4(bl[q][0], bl[q][1], bl[q][2], bl[q][3], bo + MAT);
            }
#pragma unroll
            for (int tm = 0; tm < 2; tm++)
#pragma unroll
                for (int nt = 0; nt < 8; nt++) {
                    int q = nt >> 1, o = (nt & 1) * 2;
                    mma_bf16(acc[tm][nt], ah[tm], &bh[q][o]);
                    mma_bf16(acc[tm][nt], ah[tm], &bl[q][o]);
                    mma_bf16(acc[tm][nt], al[tm], &bh[q][o]);
                }
        }
        __syncthreads();
    }

    // ---- epilogue ----
#pragma unroll
    for (int tm = 0; tm < 2; tm++) {
        int rbase = row0 + warp_m * 32 + tm * 16 + (lane >> 2);
#pragma unroll
        for (int half = 0; half < 2; half++) {
            int row_g = rbase + half * 8;
            if (row_g >= M) continue;
#pragma unroll
            for (int nt = 0; nt < 8; nt++) {
                int col = ncol0 + warp_n * 64 + nt * 8 + (lane & 3) * 2;
                float v0 = acc[tm][nt][half * 2 + 0];
                float v1 = acc[tm][nt][half * 2 + 1];
                if (bias) { v0 += bias[col]; v1 += bias[col + 1]; }
                if (RELU) { v0 = fmaxf(v0, 0.f); v1 = fmaxf(v1, 0.f); }
                if (WF32) {
                    float2 w = make_float2(v0, v1);
                    *(float2*)(Cf + (size_t)row_g * Ntot + col) = w;
                }
                if (WBF16) {
                    __nv_bfloat16 h0 = __float2bfloat16(v0);
                    __nv_bfloat16 h1 = __float2bfloat16(v1);
                    float l0 = v0 - __bfloat162float(h0);
                    float l1 = v1 - __bfloat162float(h1);
                    *(uint32_t*)(Cbh + (size_t)row_g * Ntot + col) =
                        ((uint32_t)__bfloat16_as_ushort(h1) << 16) | __bfloat16_as_ushort(h0);
                    *(uint32_t*)(Cbl + (size_t)row_g * Ntot + col) = pack_bf2(l0, l1);
                }
            }
        }
    }
}

// ================= small kernels =================
__global__ void zero_kernel(float4* p, long n4) {
    long i = (long)blockIdx.x * blockDim.x + threadIdx.x;
    if (i < n4) p[i] = make_float4(0.f, 0.f, 0.f, 0.f);
}

// hs[dst] += h[src], float4 vector atomics
__global__ void scatter_add_kernel(const float* __restrict__ h,
                                   const int* __restrict__ src,
                                   const int* __restrict__ dst,
                                   float* __restrict__ hs) {
    long idx = (long)blockIdx.x * blockDim.x + threadIdx.x;
    long e = idx >> 6;
    if (e >= N_EDGES) return;
    int q = (int)(idx & 63) << 2;
    int s = src[e];
    int d = dst[e];
    float4 v = *(const float4*)(h + (size_t)s * HID + q);
    atomicAdd((float4*)(hs + (size_t)d * HID + q), v);
}

// fp32 -> bf16 hi/lo pair (vectorized)
__global__ void conv_pair4(const float4* __restrict__ src, uint2* __restrict__ dh,
                           uint2* __restrict__ dl, long n4) {
    long i = (long)blockIdx.x * blockDim.x + threadIdx.x;
    if (i >= n4) return;
    float4 v = src[i];
    __nv_bfloat16 h0 = __float2bfloat16(v.x), h1 = __float2bfloat16(v.y);
    __nv_bfloat16 h2 = __float2bfloat16(v.z), h3 = __float2bfloat16(v.w);
    uint2 uh, ul;
    uh.x = ((uint32_t)__bfloat16_as_ushort(h1) << 16) | __bfloat16_as_ushort(h0);
    uh.y = ((uint32_t)__bfloat16_as_ushort(h3) << 16) | __bfloat16_as_ushort(h2);
    ul.x = pack_bf2(v.x - __bfloat162float(h0), v.y - __bfloat162float(h1));
    ul.y = pack_bf2(v.z - __bfloat162float(h2), v.w - __bfloat162float(h3));
    dh[i] = uh;
    dl[i] = ul;
}

__device__ __forceinline__ void split_store(float v, __nv_bfloat16* ph, __nv_bfloat16* pl) {
    __nv_bfloat16 h = __float2bfloat16(v);
    *ph = h;
    *pl = __float2bfloat16(v - __bfloat162float(h));
}

// ggc_w[s][k][n] -> wt[s][n][k]
__global__ void conv_ggc(const float* __restrict__ src, __nv_bfloat16* dh, __nv_bfloat16* dl) {
    int idx = blockIdx.x * blockDim.x + threadIdx.x;
    if (idx >= STEPS * 256 * 256) return;
    int s = idx >> 16, rem = idx & 65535;
    int nn = rem >> 8, kk = rem & 255;
    float v = src[(size_t)s * 65536 + kk * 256 + nn];
    split_store(v, dh + idx, dl + idx);
}
// Wa1[k(256)][n(128)] -> wa1t[n][k]
__global__ void conv_wa1(const float* __restrict__ src, __nv_bfloat16* dh, __nv_bfloat16* dl) {
    int idx = blockIdx.x * blockDim.x + threadIdx.x;
    if (idx >= 128 * 256) return;
    int nn = idx >> 8, kk = idx & 255;
    split_store(src[kk * 128 + nn], dh + idx, dl + idx);
}
// W_in[k(100)][n(256)] -> wint[n][k(128 padded)]
__global__ void conv_win(const float* __restrict__ src, __nv_bfloat16* dh, __nv_bfloat16* dl) {
    int idx = blockIdx.x * blockDim.x + threadIdx.x;
    if (idx >= 256 * 128) return;
    int nn = idx >> 7, kk = idx & 127;
    float v = (kk < IN_DIM) ? src[kk * 256 + nn] : 0.f;
    split_store(v, dh + idx, dl + idx);
}
// x[r][100] -> x_hi/lo[r][128 padded]
__global__ void conv_x(const float* __restrict__ x, __nv_bfloat16* dh, __nv_bfloat16* dl) {
    long idx = (long)blockIdx.x * blockDim.x + threadIdx.x;
    if (idx >= (long)N_NODES * 128) return;
    int r = (int)(idx >> 7), k = (int)(idx & 127);
    float v = (k < IN_DIM) ? x[(size_t)r * IN_DIM + k] : 0.f;
    split_store(v, dh + idx, dl + idx);
}

// GRU elementwise (+biases), fused bf16-split emission of new h
__global__ void gru_kernel(const float* __restrict__ gi, const float* __restrict__ gh,
                           const float* __restrict__ b_ih, const float* __restrict__ b_hh,
                           float* __restrict__ h, __nv_bfloat16* __restrict__ hh,
                           __nv_bfloat16* __restrict__ hl) {
    long idx = (long)blockIdx.x * blockDim.x + threadIdx.x;
    if (idx >= (long)N_NODES * 64) return;
    int n = (int)(idx >> 6);
    int d = (int)(idx & 63) << 2;
    size_t b3 = (size_t)n * 768 + d;
    float4 ir = *(const float4*)(gi + b3);
    float4 iz = *(const float4*)(gi + b3 + 256);
    float4 in_ = *(const float4*)(gi + b3 + 512);
    float4 hr = *(const float4*)(gh + b3);
    float4 hz = *(const float4*)(gh + b3 + 256);
    float4 hn = *(const float4*)(gh + b3 + 512);
    float4 bir = *(const float4*)(b_ih + d);
    float4 biz = *(const float4*)(b_ih + 256 + d);
    float4 bin_ = *(const float4*)(b_ih + 512 + d);
    float4 bhr = *(const float4*)(b_hh + d);
    float4 bhz = *(const float4*)(b_hh + 256 + d);
    float4 bhn = *(const float4*)(b_hh + 512 + d);
    size_t hb = (size_t)n * HID + d;
    float4 hv = *(const float4*)(h + hb);
    float o[4];
#pragma unroll
    for (int c = 0; c < 4; c++) {
        float xir = ((const float*)&ir)[c] + ((const float*)&bir)[c];
        float xiz = ((const float*)&iz)[c] + ((const float*)&biz)[c];
        float xin = ((const float*)&in_)[c] + ((const float*)&bin_)[c];
        float xhr = ((const float*)&hr)[c] + ((const float*)&bhr)[c];
        float xhz = ((const float*)&hz)[c] + ((const float*)&bhz)[c];
        float xhn = ((const float*)&hn)[c] + ((const float*)&bhn)[c];
        float hold = ((const float*)&hv)[c];
        float r = 1.f / (1.f + expf(-(xir + xhr)));
        float z = 1.f / (1.f + expf(-(xiz + xhz)));
        float nn = tanhf(xin + r * xhn);
        o[c] = (1.f - z) * nn + z * hold;
    }
    *(float4*)(h + hb) = make_float4(o[0], o[1], o[2], o[3]);
    __nv_bfloat16 q0 = __float2bfloat16(o[0]), q1 = __float2bfloat16(o[1]);
    __nv_bfloat16 q2 = __float2bfloat16(o[2]), q3 = __float2bfloat16(o[3]);
    uint2 uh, ul;
    uh.x = ((uint32_t)__bfloat16_as_ushort(q1) << 16) | __bfloat16_as_ushort(q0);
    uh.y = ((uint32_t)__bfloat16_as_ushort(q3) << 16) | __bfloat16_as_ushort(q2);
    ul.x = pack_bf2(o[0] - __bfloat162float(q0), o[1] - __bfloat162float(q1));
    ul.y = pack_bf2(o[2] - __bfloat162float(q2), o[3] - __bfloat162float(q3));
    *(uint2*)(hh + hb) = uh;
    *(uint2*)(hl + hb) = ul;
}

// h = relu(h), re-emit bf16 split
__global__ void relu_h_kernel(float* __restrict__ h, __nv_bfloat16* __restrict__ hh,
                              __nv_bfloat16* __restrict__ hl) {
    long idx = (long)blockIdx.x * blockDim.x + threadIdx.x;
    if (idx >= (long)N_NODES * 64) return;
    size_t b = (size_t)idx << 2;
    float4 v = *(const float4*)(h + b);
    v.x = fmaxf(v.x, 0.f); v.y = fmaxf(v.y, 0.f);
    v.z = fmaxf(v.z, 0.f); v.w = fmaxf(v.w, 0.f);
    *(float4*)(h + b) = v;
    __nv_bfloat16 q0 = __float2bfloat16(v.x), q1 = __float2bfloat16(v.y);
    __nv_bfloat16 q2 = __float2bfloat16(v.z), q3 = __float2bfloat16(v.w);
    uint2 uh, ul;
    uh.x = ((uint32_t)__bfloat16_as_ushort(q1) << 16) | __bfloat16_as_ushort(q0);
    uh.y = ((uint32_t)__bfloat16_as_ushort(q3) << 16) | __bfloat16_as_ushort(q2);
    ul.x = pack_bf2(v.x - __bfloat162float(q0), v.y - __bfloat162float(q1));
    ul.y = pack_bf2(v.z - __bfloat162float(q2), v.w - __bfloat162float(q3));
    *(uint2*)(hh + b) = uh;
    *(uint2*)(hl + b) = ul;
}

// a = sigmoid(t1 @ Wa2 + ba2)
__global__ void attn_a_kernel(const float* __restrict__ t1, const float* __restrict__ Wa2,
                              const float* __restrict__ ba2, float* __restrict__ a) {
    long idx = (long)blockIdx.x * blockDim.x + threadIdx.x;
    int warp = (int)(idx >> 5);
    int lane = (int)(idx & 31);
    if (warp >= N_NODES) return;
    float s = 0.f;
#pragma unroll
    for (int k = lane; k < HID / 2; k += 32) s += t1[(size_t)warp * (HID / 2) + k] * Wa2[k];
#pragma unroll
    for (int o = 16; o > 0; o >>= 1) s += __shfl_xor_sync(0xFFFFFFFFu, s, o);
    if (lane == 0) a[warp] = 1.f / (1.f + expf(-(s + ba2[0])));
}

__global__ void pool_kernel(const float* __restrict__ h, const float* __restrict__ a,
                            const int* __restrict__ batch, float* __restrict__ pool) {
    int g = blockIdx.x;
    int d = threadIdx.x;
    __shared__ int s_lo, s_hi;
    if (d == 0) {
        int lo = 0, hi = N_NODES;
        while (lo < hi) { int mid = (lo + hi) >> 1; if (batch[mid] < g) lo = mid + 1; else hi = mid; }
        s_lo = lo;
        lo = 0; hi = N_NODES;
        while (lo < hi) { int mid = (lo + hi) >> 1; if (batch[mid] < g + 1) lo = mid + 1; else hi = mid; }
        s_hi = lo;
    }
    __syncthreads();
    int lo = s_lo, hi = s_hi;
    float sum = 0.f, mx = 0.f;  // wx >= 0 so 0-init max matches ref
    for (int i = lo; i < hi; i++) {
        float w = h[(size_t)i * HID + d] * a[i];
        sum += w;
        mx = fmaxf(mx, w);
    }
    int cnt = hi - lo;
    pool[(size_t)g * 2 * HID + d] = sum / (float)(cnt > 1 ? cnt : 1);
    pool[(size_t)g * 2 * HID + HID + d] = (cnt > 0) ? mx : 0.f;
}

__global__ void classifier_kernel(const float* __restrict__ pool,
                                  const float* __restrict__ Wc1, const float* __restrict__ bc1,
                                  const float* __restrict__ Wc2, const float* __restrict__ bc2,
                                  const float* __restrict__ Wc3, const float* __restrict__ bc3,
                                  float* __restrict__ preds) {
    int g = blockIdx.x;
    int t = threadIdx.x;
    __shared__ float sg[2 * HID];
    __shared__ float t1[HID];
    __shared__ float t2[HID / 2];
    sg[t] = pool[(size_t)g * 2 * HID + t];
    sg[t + HID] = pool[(size_t)g * 2 * HID + HID + t];
    __syncthreads();
    {
        float acc = bc1[t];
        for (int k = 0; k < 2 * HID; k++) acc += sg[k] * Wc1[(size_t)k * HID + t];
        t1[t] = fmaxf(acc, 0.f);
    }
    __syncthreads();
    if (t < HID / 2) {
        float acc = bc2[t];
        for (int k = 0; k < HID; k++) acc += t1[k] * Wc2[(size_t)k * (HID / 2) + t];
        t2[t] = fmaxf(acc, 0.f);
    }
    __syncthreads();
    if (t < 2) {
        float acc = bc3[t];
        for (int k = 0; k < HID / 2; k++) acc += t2[k] * Wc3[(size_t)k * 2 + t];
        preds[g * 2 + t] = acc;
    }
}

// ================= launch =================
extern "C" void kernel_launch(void* const* d_in, const int* in_sizes, int n_in,
                              void* d_out, int out_size) {
    const float* x     = (const float*)d_in[0];
    const int*   edge  = (const int*)d_in[1];
    const int*   batch = (const int*)d_in[2];
    const float* W_in  = (const float*)d_in[3];
    const float* b_in  = (const float*)d_in[4];
    const float* ggc_w = (const float*)d_in[5];
    const float* W_ih  = (const float*)d_in[6];
    const float* W_hh  = (const float*)d_in[7];
    const float* b_ih  = (const float*)d_in[8];
    const float* b_hh  = (const float*)d_in[9];
    const float* Wa1   = (const float*)d_in[10];
    const float* ba1   = (const float*)d_in[11];
    const float* Wa2   = (const float*)d_in[12];
    const float* ba2   = (const float*)d_in[13];
    const float* Wc1   = (const float*)d_in[14];
    const float* bc1   = (const float*)d_in[15];
    const float* Wc2   = (const float*)d_in[16];
    const float* bc2   = (const float*)d_in[17];
    const float* Wc3   = (const float*)d_in[18];
    const float* bc3   = (const float*)d_in[19];

    float* out   = (float*)d_out;
    float* preds = out;
    float* a_out = out + N_GRAPHS * 2;

    float *h, *hs, *gi, *gh, *t1, *pool;
    __nv_bfloat16 *h_hi, *h_lo, *hs_hi, *hs_lo, *ag_hi, *ag_lo, *x_hi, *x_lo;
    __nv_bfloat16 *wih_hi, *wih_lo, *whh_hi, *whh_lo, *wt_hi, *wt_lo, *wa1_hi, *wa1_lo, *win_hi, *win_lo;
    cudaGetSymbolAddress((void**)&h, d_h);
    cudaGetSymbolAddress((void**)&hs, d_hs);
    cudaGetSymbolAddress((void**)&gi, d_gi);
    cudaGetSymbolAddress((void**)&gh, d_gh);
    cudaGetSymbolAddress((void**)&t1, d_t1);
    cudaGetSymbolAddress((void**)&pool, d_pool);
    cudaGetSymbolAddress((void**)&h_hi, d_h_hi);
    cudaGetSymbolAddress((void**)&h_lo, d_h_lo);
    cudaGetSymbolAddress((void**)&hs_hi, d_hs_hi);
    cudaGetSymbolAddress((void**)&hs_lo, d_hs_lo);
    cudaGetSymbolAddress((void**)&ag_hi, d_ag_hi);
    cudaGetSymbolAddress((void**)&ag_lo, d_ag_lo);
    cudaGetSymbolAddress((void**)&x_hi, d_x_hi);
    cudaGetSymbolAddress((void**)&x_lo, d_x_lo);
    cudaGetSymbolAddress((void**)&wih_hi, d_wih_hi);
    cudaGetSymbolAddress((void**)&wih_lo, d_wih_lo);
    cudaGetSymbolAddress((void**)&whh_hi, d_whh_hi);
    cudaGetSymbolAddress((void**)&whh_lo, d_whh_lo);
    cudaGetSymbolAddress((void**)&wt_hi, d_wt_hi);
    cudaGetSymbolAddress((void**)&wt_lo, d_wt_lo);
    cudaGetSymbolAddress((void**)&wa1_hi, d_wa1_hi);
    cudaGetSymbolAddress((void**)&wa1_lo, d_wa1_lo);
    cudaGetSymbolAddress((void**)&win_hi, d_win_hi);
    cudaGetSymbolAddress((void**)&win_lo, d_win_lo);

    const int* src = edge;
    const int* dst = edge + N_EDGES;

    const int SMEM = 2 * 4 * (128 * 80);  // 81920 B
    cudaFuncSetAttribute(mma_gemm<128, true, true, true>,
                         cudaFuncAttributeMaxDynamicSharedMemorySize, SMEM);
    cudaFuncSetAttribute(mma_gemm<256, false, true, false>,
                         cudaFuncAttributeMaxDynamicSharedMemorySize, SMEM);
    cudaFuncSetAttribute(mma_gemm<256, true, false, false>,
                         cudaFuncAttributeMaxDynamicSharedMemorySize, SMEM);
    cudaFuncSetAttribute(mma_gemm<256, true, false, true>,
                         cudaFuncAttributeMaxDynamicSharedMemorySize, SMEM);

    const int MT = (N_NODES + 127) / 128;  // 391

    // ---- weight / input conversions ----
    conv_pair4<<<(768 * 256 / 4 + 255) / 256, 256>>>((const float4*)W_ih, (uint2*)wih_hi, (uint2*)wih_lo, 768 * 256 / 4);
    conv_pair4<<<(768 * 256 / 4 + 255) / 256, 256>>>((const float4*)W_hh, (uint2*)whh_hi, (uint2*)whh_lo, 768 * 256 / 4);
    conv_ggc<<<(STEPS * 65536 + 255) / 256, 256>>>(ggc_w, wt_hi, wt_lo);
    conv_wa1<<<(128 * 256 + 255) / 256, 256>>>(Wa1, wa1_hi, wa1_lo);
    conv_win<<<(256 * 128 + 255) / 256, 256>>>(W_in, win_hi, win_lo);
    {
        long tot = (long)N_NODES * 128;
        conv_x<<<(unsigned)((tot + 255) / 256), 256>>>(x, x_hi, x_lo);
    }

    // ---- input projection: h = relu(x @ W_in + b_in), fused bf16 split ----
    mma_gemm<128, true, true, true><<<dim3(2, MT), 256, SMEM>>>(
        x_hi, x_lo, win_hi, win_lo, b_in, h, h_hi, h_lo, N_NODES, HID);

    long n4_hs = (long)N_NODES * HID / 4;
    for (int s = 0; s < STEPS; s++) {
        zero_kernel<<<(unsigned)((n4_hs + 255) / 256), 256>>>((float4*)hs, n4_hs);
        {
            long tot = (long)N_EDGES * 64;
            scatter_add_kernel<<<(unsigned)((tot + 255) / 256), 256>>>(h, src, dst, hs);
        }
        conv_pair4<<<(unsigned)((n4_hs + 255) / 256), 256>>>((const float4*)hs, (uint2*)hs_hi, (uint2*)hs_lo, n4_hs);
        // agg = hs @ w[s]  (bf16-split output only)
        mma_gemm<256, false, true, false><<<dim3(2, MT), 256, SMEM>>>(
            hs_hi, hs_lo, wt_hi + (size_t)s * 65536, wt_lo + (size_t)s * 65536,
            nullptr, nullptr, ag_hi, ag_lo, N_NODES, HID);
        // gi = agg @ W_ih^T ; gh = h @ W_hh^T
        mma_gemm<256, true, false, false><<<dim3(6, MT), 256, SMEM>>>(
            ag_hi, ag_lo, wih_hi, wih_lo, nullptr, gi, nullptr, nullptr, N_NODES, 3 * HID);
        mma_gemm<256, true, false, false><<<dim3(6, MT), 256, SMEM>>>(
            h_hi, h_lo, whh_hi, whh_lo, nullptr, gh, nullptr, nullptr, N_NODES, 3 * HID);
        {
            long tot = (long)N_NODES * 64;
            gru_kernel<<<(unsigned)((tot + 255) / 256), 256>>>(gi, gh, b_ih, b_hh, h, h_hi, h_lo);
        }
    }

    {
        long tot = (long)N_NODES * 64;
        relu_h_kernel<<<(unsigned)((tot + 255) / 256), 256>>>(h, h_hi, h_lo);
    }

    // attention: t1 = relu(h @ Wa1 + ba1)
    mma_gemm<256, true, false, true><<<dim3(1, MT), 256, SMEM>>>(
        h_hi, h_lo, wa1_hi, wa1_lo, ba1, t1, nullptr, nullptr, N_NODES, HID / 2);
    {
        long tot = (long)N_NODES * 32;
        attn_a_kernel<<<(unsigned)((tot + 255) / 256), 256>>>(t1, Wa2, ba2, a_out);
    }

    pool_kernel<<<N_GRAPHS, HID>>>(h, a_out, batch, pool);
    classifier_kernel<<<N_GRAPHS, 256>>>(pool, Wc1, bc1, Wc2, bc2, Wc3, bc3, preds);
}